// round 2
// baseline (speedup 1.0000x reference)
#include <cuda_runtime.h>
#include <math.h>
#include <stdint.h>

// Problem dims (fixed)
#define Sdim 1024
#define Bdim 4
#define Ddim 1024
#define Hn   16
#define DHdim 64
#define Tdim (Sdim*Bdim)      // 4096 tokens
#define D3   (3*Ddim)         // 3072

// Scratch (bss, no allocation)
__device__ float g_h  [(size_t)Tdim * Ddim];   // LN1 output
__device__ float g_qkv[(size_t)Tdim * D3];     // qkv projection
__device__ float g_o  [(size_t)Tdim * Ddim];   // attention output (token-major, head cols)
__device__ float g_xo [(size_t)Tdim * Ddim];   // x + out_proj(attn)

__device__ __forceinline__ float warp_sum_f(float v) {
#pragma unroll
    for (int o = 16; o; o >>= 1) v += __shfl_xor_sync(0xffffffffu, v, o);
    return v;
}

// ---------------------------------------------------------------------------
// LayerNorm: one block (256 thr) per token row of D=1024. float4 per thread.
// ---------------------------------------------------------------------------
__global__ void __launch_bounds__(256) ln_kernel(
    const float* __restrict__ x, const float* __restrict__ w,
    const float* __restrict__ b, float* __restrict__ out)
{
    int t = blockIdx.x;
    int tid = threadIdx.x;
    const float4 v = reinterpret_cast<const float4*>(x + (size_t)t * Ddim)[tid];

    float s  = v.x + v.y + v.z + v.w;
    float sq = v.x*v.x + v.y*v.y + v.z*v.z + v.w*v.w;
    s  = warp_sum_f(s);
    sq = warp_sum_f(sq);

    __shared__ float sm[16];
    __shared__ float stats[2];
    int warp = tid >> 5, lane = tid & 31;
    if (lane == 0) { sm[warp] = s; sm[warp + 8] = sq; }
    __syncthreads();
    if (tid == 0) {
        float a = 0.f, c = 0.f;
#pragma unroll
        for (int i = 0; i < 8; i++) { a += sm[i]; c += sm[i + 8]; }
        float mu  = a * (1.f / Ddim);
        float var = c * (1.f / Ddim) - mu * mu;
        stats[0] = mu;
        stats[1] = rsqrtf(var + 1e-5f);
    }
    __syncthreads();
    float mu = stats[0], rs = stats[1];

    const float4 wv = reinterpret_cast<const float4*>(w)[tid];
    const float4 bv = reinterpret_cast<const float4*>(b)[tid];
    float4 o;
    o.x = (v.x - mu) * rs * wv.x + bv.x;
    o.y = (v.y - mu) * rs * wv.y + bv.y;
    o.z = (v.z - mu) * rs * wv.z + bv.z;
    o.w = (v.w - mu) * rs * wv.w + bv.w;
    reinterpret_cast<float4*>(out + (size_t)t * Ddim)[tid] = o;
}

// ---------------------------------------------------------------------------
// SGEMM (NT), double-buffered: C[m,n] = sum_k A[m,k]*W[n,k] + bias[n] (+res)
// A: MxK row-major, W: NxK row-major. 128x128 tile, BK=16, 8x8 per thread.
// Pipeline per K-tile: LDG(t+1) -> FFMA(t) -> STS(t+1) -> BAR
// ---------------------------------------------------------------------------
template <int RES>
__global__ void __launch_bounds__(256) gemm_nt(
    const float* __restrict__ A, const float* __restrict__ W,
    const float* __restrict__ bias, const float* __restrict__ res,
    float* __restrict__ C, int M, int N, int K)
{
    __shared__ float As[2][16][128];
    __shared__ float Bs[2][16][128];

    const int m0 = blockIdx.y * 128;
    const int n0 = blockIdx.x * 128;
    const int tid = threadIdx.x;
    const int ty = tid >> 4;      // 0..15
    const int tx = tid & 15;      // 0..15

    // Per-tile load assignment: 2 float4 per array per thread.
    // vec id v in [0,512): row = v>>2 (0..127), c4 = (v&3)*4 (k offset)
    int lrow[2], lc4[2];
#pragma unroll
    for (int it = 0; it < 2; it++) {
        int v = tid + it * 256;
        lrow[it] = v >> 2;
        lc4[it]  = (v & 3) * 4;
    }

    float acc[8][8];
#pragma unroll
    for (int i = 0; i < 8; i++)
#pragma unroll
        for (int j = 0; j < 8; j++) acc[i][j] = 0.f;

    float4 ra[2], rb[2];

    // prologue: load tile 0 into registers, store into buffer 0
#pragma unroll
    for (int it = 0; it < 2; it++) {
        ra[it] = *reinterpret_cast<const float4*>(A + (size_t)(m0 + lrow[it]) * K + lc4[it]);
        rb[it] = *reinterpret_cast<const float4*>(W + (size_t)(n0 + lrow[it]) * K + lc4[it]);
    }
#pragma unroll
    for (int it = 0; it < 2; it++) {
        As[0][lc4[it] + 0][lrow[it]] = ra[it].x; As[0][lc4[it] + 1][lrow[it]] = ra[it].y;
        As[0][lc4[it] + 2][lrow[it]] = ra[it].z; As[0][lc4[it] + 3][lrow[it]] = ra[it].w;
        Bs[0][lc4[it] + 0][lrow[it]] = rb[it].x; Bs[0][lc4[it] + 1][lrow[it]] = rb[it].y;
        Bs[0][lc4[it] + 2][lrow[it]] = rb[it].z; Bs[0][lc4[it] + 3][lrow[it]] = rb[it].w;
    }
    __syncthreads();

    const int nTiles = K >> 4;
    for (int t = 0; t < nTiles; t++) {
        const int cur = t & 1;
        const int nxt = cur ^ 1;

        // issue global loads for tile t+1 (latency hides under compute below)
        if (t + 1 < nTiles) {
            int k0 = (t + 1) << 4;
#pragma unroll
            for (int it = 0; it < 2; it++) {
                ra[it] = *reinterpret_cast<const float4*>(A + (size_t)(m0 + lrow[it]) * K + k0 + lc4[it]);
                rb[it] = *reinterpret_cast<const float4*>(W + (size_t)(n0 + lrow[it]) * K + k0 + lc4[it]);
            }
        }

        // compute on current buffer
#pragma unroll
        for (int k = 0; k < 16; k++) {
            float a[8], b[8];
            *reinterpret_cast<float4*>(a)     = *reinterpret_cast<const float4*>(&As[cur][k][ty * 8]);
            *reinterpret_cast<float4*>(a + 4) = *reinterpret_cast<const float4*>(&As[cur][k][ty * 8 + 4]);
            *reinterpret_cast<float4*>(b)     = *reinterpret_cast<const float4*>(&Bs[cur][k][tx * 8]);
            *reinterpret_cast<float4*>(b + 4) = *reinterpret_cast<const float4*>(&Bs[cur][k][tx * 8 + 4]);
#pragma unroll
            for (int i = 0; i < 8; i++)
#pragma unroll
                for (int j = 0; j < 8; j++) acc[i][j] += a[i] * b[j];
        }

        // stage tile t+1 into the other buffer
        if (t + 1 < nTiles) {
#pragma unroll
            for (int it = 0; it < 2; it++) {
                As[nxt][lc4[it] + 0][lrow[it]] = ra[it].x; As[nxt][lc4[it] + 1][lrow[it]] = ra[it].y;
                As[nxt][lc4[it] + 2][lrow[it]] = ra[it].z; As[nxt][lc4[it] + 3][lrow[it]] = ra[it].w;
                Bs[nxt][lc4[it] + 0][lrow[it]] = rb[it].x; Bs[nxt][lc4[it] + 1][lrow[it]] = rb[it].y;
                Bs[nxt][lc4[it] + 2][lrow[it]] = rb[it].z; Bs[nxt][lc4[it] + 3][lrow[it]] = rb[it].w;
            }
            __syncthreads();
        }
    }

#pragma unroll
    for (int i = 0; i < 8; i++) {
        int row = m0 + ty * 8 + i;
#pragma unroll
        for (int jj = 0; jj < 8; jj += 4) {
            int col = n0 + tx * 8 + jj;
            float4 c;
            c.x = acc[i][jj + 0] + bias[col + 0];
            c.y = acc[i][jj + 1] + bias[col + 1];
            c.z = acc[i][jj + 2] + bias[col + 2];
            c.w = acc[i][jj + 3] + bias[col + 3];
            if (RES) {
                float4 r = *reinterpret_cast<const float4*>(res + (size_t)row * N + col);
                c.x += r.x; c.y += r.y; c.z += r.z; c.w += r.w;
            }
            *reinterpret_cast<float4*>(C + (size_t)row * N + col) = c;
        }
    }
}

// ---------------------------------------------------------------------------
// Causal flash attention. grid = (S/64 q-tiles, B*H). 256 threads.
// Thread (rg,cg) owns a 4x4 patch of the 64x64 score/output tiles.
// Online softmax; o accumulated in registers; writes o in [T, D] layout.
// ---------------------------------------------------------------------------
#define APITCH 65
__global__ void __launch_bounds__(256) attn_kernel(
    const float* __restrict__ qkv, float* __restrict__ o_out)
{
    extern __shared__ float smf[];
    float* Qs = smf;                    // 64 * APITCH
    float* Ks = Qs + 64 * APITCH;
    float* Vs = Ks + 64 * APITCH;
    float* Ps = Vs + 64 * APITCH;

    const int qt = blockIdx.x;
    const int bh = blockIdx.y;
    const int b = bh >> 4;
    const int h = bh & 15;
    const int tid = threadIdx.x;
    const int rg = tid >> 4;    // row group: rows rg*4 .. rg*4+3
    const int cg = tid & 15;    // col group: cols cg*4 .. cg*4+3

    // Load Q tile (pre-scaled by Dh^-0.5 = 0.125)
    for (int e = tid; e < 64 * 64; e += 256) {
        int r = e >> 6, c = e & 63;
        int t = (qt * 64 + r) * Bdim + b;
        Qs[r * APITCH + c] = qkv[(size_t)t * D3 + h * DHdim + c] * 0.125f;
    }

    float m[4], l[4], o[4][4];
#pragma unroll
    for (int i = 0; i < 4; i++) {
        m[i] = -INFINITY; l[i] = 0.f;
#pragma unroll
        for (int j = 0; j < 4; j++) o[i][j] = 0.f;
    }

    for (int kt = 0; kt <= qt; kt++) {
        __syncthreads();   // previous tile fully consumed (and Q visible on 1st iter)
        for (int e = tid; e < 64 * 64; e += 256) {
            int r = e >> 6, c = e & 63;
            int t = (kt * 64 + r) * Bdim + b;
            Ks[r * APITCH + c] = qkv[(size_t)t * D3 + Ddim     + h * DHdim + c];
            Vs[r * APITCH + c] = qkv[(size_t)t * D3 + 2 * Ddim + h * DHdim + c];
        }
        __syncthreads();

        float s[4][4];
#pragma unroll
        for (int i = 0; i < 4; i++)
#pragma unroll
            for (int j = 0; j < 4; j++) s[i][j] = 0.f;

#pragma unroll 4
        for (int k = 0; k < 64; k++) {
            float qv[4], kv[4];
#pragma unroll
            for (int i = 0; i < 4; i++) qv[i] = Qs[(rg * 4 + i) * APITCH + k];
#pragma unroll
            for (int j = 0; j < 4; j++) kv[j] = Ks[(cg * 4 + j) * APITCH + k];
#pragma unroll
            for (int i = 0; i < 4; i++)
#pragma unroll
                for (int j = 0; j < 4; j++) s[i][j] += qv[i] * kv[j];
        }

        if (kt == qt) {
#pragma unroll
            for (int i = 0; i < 4; i++)
#pragma unroll
                for (int j = 0; j < 4; j++)
                    if (cg * 4 + j > rg * 4 + i) s[i][j] = -INFINITY;
        }

        // online softmax (reduce over the 16 cg lanes of this row group)
#pragma unroll
        for (int i = 0; i < 4; i++) {
            float mx = fmaxf(fmaxf(s[i][0], s[i][1]), fmaxf(s[i][2], s[i][3]));
#pragma unroll
            for (int d = 1; d < 16; d <<= 1) mx = fmaxf(mx, __shfl_xor_sync(0xffffffffu, mx, d));
            float mn = fmaxf(m[i], mx);
            float scale = expf(m[i] - mn);
            float ls = 0.f;
#pragma unroll
            for (int j = 0; j < 4; j++) { s[i][j] = expf(s[i][j] - mn); ls += s[i][j]; }
#pragma unroll
            for (int d = 1; d < 16; d <<= 1) ls += __shfl_xor_sync(0xffffffffu, ls, d);
            l[i] = l[i] * scale + ls;
            m[i] = mn;
#pragma unroll
            for (int j = 0; j < 4; j++) {
                o[i][j] *= scale;
                Ps[(rg * 4 + i) * APITCH + cg * 4 + j] = s[i][j];
            }
        }
        __syncthreads();

        // O += P @ V
#pragma unroll 4
        for (int c = 0; c < 64; c++) {
            float pv[4], vv[4];
#pragma unroll
            for (int i = 0; i < 4; i++) pv[i] = Ps[(rg * 4 + i) * APITCH + c];
#pragma unroll
            for (int j = 0; j < 4; j++) vv[j] = Vs[c * APITCH + cg * 4 + j];
#pragma unroll
            for (int i = 0; i < 4; i++)
#pragma unroll
                for (int j = 0; j < 4; j++) o[i][j] += pv[i] * vv[j];
        }
    }

#pragma unroll
    for (int i = 0; i < 4; i++) {
        int r = rg * 4 + i;
        int t = (qt * 64 + r) * Bdim + b;
        float inv = 1.f / l[i];
#pragma unroll
        for (int j = 0; j < 4; j++)
            o_out[(size_t)t * Ddim + h * DHdim + cg * 4 + j] = o[i][j] * inv;
    }
}

// ---------------------------------------------------------------------------
// Fused: LN2 -> router logits (E=3) -> top2 gate = sigmoid(l_hi - l_mid)
//        -> out = x_attn * gate. One block per token.
// ---------------------------------------------------------------------------
__global__ void __launch_bounds__(256) final_kernel(
    const float* __restrict__ xo, const float* __restrict__ w,
    const float* __restrict__ bprm, const float* __restrict__ gate_w,
    float* __restrict__ out, float* __restrict__ logits)
{
    int t = blockIdx.x;
    int tid = threadIdx.x;
    const float4 v = reinterpret_cast<const float4*>(xo + (size_t)t * Ddim)[tid];

    float s  = v.x + v.y + v.z + v.w;
    float sq = v.x*v.x + v.y*v.y + v.z*v.z + v.w*v.w;
    s  = warp_sum_f(s);
    sq = warp_sum_f(sq);

    __shared__ float sm[16];
    __shared__ float red[3][8];
    __shared__ float bc[3];      // mu, rstd, gate
    int warp = tid >> 5, lane = tid & 31;
    if (lane == 0) { sm[warp] = s; sm[warp + 8] = sq; }
    __syncthreads();
    if (tid == 0) {
        float a = 0.f, c = 0.f;
#pragma unroll
        for (int i = 0; i < 8; i++) { a += sm[i]; c += sm[i + 8]; }
        float mu = a * (1.f / Ddim);
        float var = c * (1.f / Ddim) - mu * mu;
        bc[0] = mu;
        bc[1] = rsqrtf(var + 1e-5f);
    }
    __syncthreads();
    float mu = bc[0], rs = bc[1];

    const float4 wv = reinterpret_cast<const float4*>(w)[tid];
    const float4 bv = reinterpret_cast<const float4*>(bprm)[tid];
    float hs[4];
    hs[0] = (v.x - mu) * rs * wv.x + bv.x;
    hs[1] = (v.y - mu) * rs * wv.y + bv.y;
    hs[2] = (v.z - mu) * rs * wv.z + bv.z;
    hs[3] = (v.w - mu) * rs * wv.w + bv.w;

    int d = tid * 4;
    float a0 = 0.f, a1 = 0.f, a2 = 0.f;
#pragma unroll
    for (int j = 0; j < 4; j++) {
        a0 += hs[j] * gate_w[0 * Ddim + d + j];
        a1 += hs[j] * gate_w[1 * Ddim + d + j];
        a2 += hs[j] * gate_w[2 * Ddim + d + j];
    }
    a0 = warp_sum_f(a0); a1 = warp_sum_f(a1); a2 = warp_sum_f(a2);
    if (lane == 0) { red[0][warp] = a0; red[1][warp] = a1; red[2][warp] = a2; }
    __syncthreads();
    if (tid == 0) {
        float l0 = 0.f, l1 = 0.f, l2 = 0.f;
#pragma unroll
        for (int i = 0; i < 8; i++) { l0 += red[0][i]; l1 += red[1][i]; l2 += red[2][i]; }
        logits[(size_t)t * 3 + 0] = l0;
        logits[(size_t)t * 3 + 1] = l1;
        logits[(size_t)t * 3 + 2] = l2;
        float hi  = fmaxf(l0, fmaxf(l1, l2));
        float lo  = fminf(l0, fminf(l1, l2));
        float mid = l0 + l1 + l2 - hi - lo;
        bc[2] = 1.f / (1.f + expf(mid - hi));   // p_top / (p_top + p_2nd)
    }
    __syncthreads();
    float gate = bc[2];
    float4 ov;
    ov.x = v.x * gate; ov.y = v.y * gate; ov.z = v.z * gate; ov.w = v.w * gate;
    reinterpret_cast<float4*>(out + (size_t)t * Ddim)[tid] = ov;
}

// ---------------------------------------------------------------------------
extern "C" void kernel_launch(void* const* d_in, const int* in_sizes, int n_in,
                              void* d_out, int out_size)
{
    const float* x          = (const float*)d_in[0];
    const float* ln1_w      = (const float*)d_in[1];
    const float* ln1_b      = (const float*)d_in[2];
    const float* ln2_w      = (const float*)d_in[3];
    const float* ln2_b      = (const float*)d_in[4];
    const float* in_proj_w  = (const float*)d_in[5];
    const float* in_proj_b  = (const float*)d_in[6];
    const float* out_proj_w = (const float*)d_in[7];
    const float* out_proj_b = (const float*)d_in[8];
    const float* gate_w     = (const float*)d_in[9];
    // d_in[10..13] = fc_w, fc_b, proj_w, proj_b — DEAD in the reference output.

    float* out    = (float*)d_out;
    float* logits = out + (size_t)Tdim * Ddim;

    float *h, *qkv, *o, *xo;
    cudaGetSymbolAddress((void**)&h,   g_h);
    cudaGetSymbolAddress((void**)&qkv, g_qkv);
    cudaGetSymbolAddress((void**)&o,   g_o);
    cudaGetSymbolAddress((void**)&xo,  g_xo);

    // 1) LN1
    ln_kernel<<<Tdim, 256>>>(x, ln1_w, ln1_b, h);

    // 2) QKV = LN1(x) @ in_proj_w.T + b
    gemm_nt<0><<<dim3(D3 / 128, Tdim / 128), 256>>>(
        h, in_proj_w, in_proj_b, nullptr, qkv, Tdim, D3, Ddim);

    // 3) causal attention
    const int attn_smem = 4 * 64 * APITCH * (int)sizeof(float);
    cudaFuncSetAttribute(attn_kernel, cudaFuncAttributeMaxDynamicSharedMemorySize, attn_smem);
    attn_kernel<<<dim3(Sdim / 64, Bdim * Hn), 256, attn_smem>>>(qkv, o);

    // 4) x_attn = x + attn @ out_proj_w.T + b
    gemm_nt<1><<<dim3(Ddim / 128, Tdim / 128), 256>>>(
        o, out_proj_w, out_proj_b, x, xo, Tdim, Ddim, Ddim);

    // 5) LN2 -> router logits -> gate -> out
    final_kernel<<<Tdim, 256>>>(xo, ln2_w, ln2_b, gate_w, out, logits);
}

// round 9
// speedup vs baseline: 1.4216x; 1.4216x over previous
#include <cuda_runtime.h>
#include <cuda_bf16.h>
#include <math.h>
#include <stdint.h>

// Problem dims (fixed)
#define Sdim 1024
#define Bdim 4
#define Ddim 1024
#define Hn   16
#define DHdim 64
#define Tdim (Sdim*Bdim)      // 4096 tokens
#define D3   (3*Ddim)         // 3072

// Scratch (bss, no allocation)
__device__ float g_h  [(size_t)Tdim * Ddim];
__device__ float g_qkv[(size_t)Tdim * D3];
__device__ float g_o  [(size_t)Tdim * Ddim];
__device__ float g_xo [(size_t)Tdim * Ddim];

__device__ __forceinline__ float warp_sum_f(float v) {
#pragma unroll
    for (int o = 16; o; o >>= 1) v += __shfl_xor_sync(0xffffffffu, v, o);
    return v;
}

// ---------------------------------------------------------------------------
// LayerNorm
// ---------------------------------------------------------------------------
__global__ void __launch_bounds__(256) ln_kernel(
    const float* __restrict__ x, const float* __restrict__ w,
    const float* __restrict__ b, float* __restrict__ out)
{
    int t = blockIdx.x;
    int tid = threadIdx.x;
    const float4 v = reinterpret_cast<const float4*>(x + (size_t)t * Ddim)[tid];

    float s  = v.x + v.y + v.z + v.w;
    float sq = v.x*v.x + v.y*v.y + v.z*v.z + v.w*v.w;
    s  = warp_sum_f(s);
    sq = warp_sum_f(sq);

    __shared__ float sm[16];
    __shared__ float stats[2];
    int warp = tid >> 5, lane = tid & 31;
    if (lane == 0) { sm[warp] = s; sm[warp + 8] = sq; }
    __syncthreads();
    if (tid == 0) {
        float a = 0.f, c = 0.f;
#pragma unroll
        for (int i = 0; i < 8; i++) { a += sm[i]; c += sm[i + 8]; }
        float mu  = a * (1.f / Ddim);
        float var = c * (1.f / Ddim) - mu * mu;
        stats[0] = mu;
        stats[1] = rsqrtf(var + 1e-5f);
    }
    __syncthreads();
    float mu = stats[0], rs = stats[1];

    const float4 wv = reinterpret_cast<const float4*>(w)[tid];
    const float4 bv = reinterpret_cast<const float4*>(b)[tid];
    float4 o;
    o.x = (v.x - mu) * rs * wv.x + bv.x;
    o.y = (v.y - mu) * rs * wv.y + bv.y;
    o.z = (v.z - mu) * rs * wv.z + bv.z;
    o.w = (v.w - mu) * rs * wv.w + bv.w;
    reinterpret_cast<float4*>(out + (size_t)t * Ddim)[tid] = o;
}

// ---------------------------------------------------------------------------
// Tensor-core GEMM via mma.sync (baseline PTX, no 'a' features).
// C = A @ W^T + bias (+res). Split-bf16: A=Ahi+Alo, W=Whi+Wlo,
// D += AhiWhi + AhiWlo + AloWhi (fp32 accum).
// CTA 128x128, BK=32, 8 warps (each 32m x 64n), double-buffered smem.
// Smem rows padded to 20 words (16 data + 4) -> conflict-free fragment LDS.
// ---------------------------------------------------------------------------
#define GM_BK   32
#define GM_ROWW 20u                  // uint32 words per smem row
#define GM_AHI  0u
#define GM_ALO  2560u                // 128*20
#define GM_BHI  5120u
#define GM_BLO  7680u
#define GM_BUFW 10240u               // words per buffer
#define GM_SMEM_BYTES (2 * 10240 * 4)  // 81920

__device__ __forceinline__ uint32_t pk_bf16x2(__nv_bfloat16 lo, __nv_bfloat16 hi) {
    uint16_t a = *reinterpret_cast<uint16_t*>(&lo);
    uint16_t b = *reinterpret_cast<uint16_t*>(&hi);
    return (uint32_t)a | ((uint32_t)b << 16);
}

__device__ __forceinline__ void mma16816(float* c, const uint32_t* a, uint32_t b0, uint32_t b1) {
    asm volatile(
        "mma.sync.aligned.m16n8k16.row.col.f32.bf16.bf16.f32 "
        "{%0,%1,%2,%3}, {%4,%5,%6,%7}, {%8,%9}, {%0,%1,%2,%3};"
        : "+f"(c[0]), "+f"(c[1]), "+f"(c[2]), "+f"(c[3])
        : "r"(a[0]), "r"(a[1]), "r"(a[2]), "r"(a[3]), "r"(b0), "r"(b1));
}

__device__ __forceinline__ void gm_ldg(const float* __restrict__ A, const float* __restrict__ W,
                                       int m0, int n0, int K, int k0, int tid,
                                       float4* ra, float4* rw) {
#pragma unroll
    for (int it = 0; it < 4; it++) {
        int v = tid + it * 256;           // 0..1023: 128 rows x 8 float4
        int row = v >> 3;
        int c4  = (v & 7) * 4;
        ra[it] = *reinterpret_cast<const float4*>(A + (size_t)(m0 + row) * K + k0 + c4);
        rw[it] = *reinterpret_cast<const float4*>(W + (size_t)(n0 + row) * K + k0 + c4);
    }
}

__device__ __forceinline__ void gm_cvt_sts(uint32_t* smw, uint32_t bufw, int tid,
                                           const float4* ra, const float4* rw) {
#pragma unroll
    for (int it = 0; it < 4; it++) {
        int v = tid + it * 256;
        int row = v >> 3;
        int f4  = v & 7;
        uint32_t wb = bufw + (uint32_t)row * GM_ROWW + (uint32_t)f4 * 2u;

        float fa[4] = {ra[it].x, ra[it].y, ra[it].z, ra[it].w};
        float fw[4] = {rw[it].x, rw[it].y, rw[it].z, rw[it].w};
        __nv_bfloat16 ah[4], al[4], wh[4], wl[4];
#pragma unroll
        for (int j = 0; j < 4; j++) {
            ah[j] = __float2bfloat16(fa[j]);
            al[j] = __float2bfloat16(fa[j] - __bfloat162float(ah[j]));
            wh[j] = __float2bfloat16(fw[j]);
            wl[j] = __float2bfloat16(fw[j] - __bfloat162float(wh[j]));
        }
        smw[wb + GM_AHI + 0] = pk_bf16x2(ah[0], ah[1]);
        smw[wb + GM_AHI + 1] = pk_bf16x2(ah[2], ah[3]);
        smw[wb + GM_ALO + 0] = pk_bf16x2(al[0], al[1]);
        smw[wb + GM_ALO + 1] = pk_bf16x2(al[2], al[3]);
        smw[wb + GM_BHI + 0] = pk_bf16x2(wh[0], wh[1]);
        smw[wb + GM_BHI + 1] = pk_bf16x2(wh[2], wh[3]);
        smw[wb + GM_BLO + 0] = pk_bf16x2(wl[0], wl[1]);
        smw[wb + GM_BLO + 1] = pk_bf16x2(wl[2], wl[3]);
    }
}

template <int RES>
__global__ void __launch_bounds__(256) gemm_mma(
    const float* __restrict__ A, const float* __restrict__ W,
    const float* __restrict__ bias, const float* __restrict__ res,
    float* __restrict__ C, int M, int N, int K)
{
    extern __shared__ uint32_t smw[];
    const int tid  = threadIdx.x;
    const int wid  = tid >> 5;
    const int lane = tid & 31;
    const int g    = lane >> 2;       // 0..7
    const int tig  = lane & 3;        // 0..3
    const int m0 = blockIdx.y * 128;
    const int n0 = blockIdx.x * 128;
    const int wm = (wid & 3) * 32;    // warp m offset in tile
    const int wn = (wid >> 2) * 64;   // warp n offset in tile

    float acc[2][8][4];
#pragma unroll
    for (int mt = 0; mt < 2; mt++)
#pragma unroll
        for (int nt = 0; nt < 8; nt++)
#pragma unroll
            for (int q = 0; q < 4; q++) acc[mt][nt][q] = 0.f;

    float4 ra[4], rw[4];
    gm_ldg(A, W, m0, n0, K, 0, tid, ra, rw);
    gm_cvt_sts(smw, 0, tid, ra, rw);
    __syncthreads();

    const int NC = K / GM_BK;         // 32
    for (int c = 0; c < NC; c++) {
        const uint32_t cur = (uint32_t)(c & 1) * GM_BUFW;

        if (c + 1 < NC) gm_ldg(A, W, m0, n0, K, (c + 1) * GM_BK, tid, ra, rw);

        // compute on cur: 2 k16 steps
#pragma unroll
        for (int ks = 0; ks < 2; ks++) {
            const uint32_t kw = (uint32_t)(ks * 8) + (uint32_t)tig;
            uint32_t ah[2][4], al[2][4];
#pragma unroll
            for (int mt = 0; mt < 2; mt++) {
                uint32_t r0 = cur + (uint32_t)(wm + mt * 16 + g) * GM_ROWW + kw;
                uint32_t r8 = r0 + 8u * GM_ROWW;
                ah[mt][0] = smw[GM_AHI + r0];
                ah[mt][1] = smw[GM_AHI + r8];
                ah[mt][2] = smw[GM_AHI + r0 + 4];
                ah[mt][3] = smw[GM_AHI + r8 + 4];
                al[mt][0] = smw[GM_ALO + r0];
                al[mt][1] = smw[GM_ALO + r8];
                al[mt][2] = smw[GM_ALO + r0 + 4];
                al[mt][3] = smw[GM_ALO + r8 + 4];
            }
#pragma unroll
            for (int nt = 0; nt < 8; nt++) {
                uint32_t rb = cur + (uint32_t)(wn + nt * 8 + g) * GM_ROWW + kw;
                uint32_t bh0 = smw[GM_BHI + rb];
                uint32_t bh1 = smw[GM_BHI + rb + 4];
                uint32_t bl0 = smw[GM_BLO + rb];
                uint32_t bl1 = smw[GM_BLO + rb + 4];
#pragma unroll
                for (int mt = 0; mt < 2; mt++) {
                    mma16816(acc[mt][nt], ah[mt], bh0, bh1);
                    mma16816(acc[mt][nt], ah[mt], bl0, bl1);
                    mma16816(acc[mt][nt], al[mt], bh0, bh1);
                }
            }
        }

        if (c + 1 < NC) {
            __syncthreads();   // all warps done reading cur's sibling? (see note) — separates compute(c) from sts into the other buffer next iter
            gm_cvt_sts(smw, (uint32_t)((c + 1) & 1) * GM_BUFW, tid, ra, rw);
            __syncthreads();
        }
    }

    // epilogue
#pragma unroll
    for (int mt = 0; mt < 2; mt++) {
        int r0 = m0 + wm + mt * 16 + g;
        int r1 = r0 + 8;
#pragma unroll
        for (int nt = 0; nt < 8; nt++) {
            int col = n0 + wn + nt * 8 + tig * 2;
            float2 o0, o1;
            o0.x = acc[mt][nt][0] + bias[col];
            o0.y = acc[mt][nt][1] + bias[col + 1];
            o1.x = acc[mt][nt][2] + bias[col];
            o1.y = acc[mt][nt][3] + bias[col + 1];
            if (RES) {
                float2 q0 = *reinterpret_cast<const float2*>(res + (size_t)r0 * N + col);
                float2 q1 = *reinterpret_cast<const float2*>(res + (size_t)r1 * N + col);
                o0.x += q0.x; o0.y += q0.y;
                o1.x += q1.x; o1.y += q1.y;
            }
            *reinterpret_cast<float2*>(C + (size_t)r0 * N + col) = o0;
            *reinterpret_cast<float2*>(C + (size_t)r1 * N + col) = o1;
        }
    }
}

// ---------------------------------------------------------------------------
// Causal flash attention. __expf in softmax (fast MUFU.EX2 path).
// ---------------------------------------------------------------------------
#define APITCH 65
__global__ void __launch_bounds__(256) attn_kernel(
    const float* __restrict__ qkv, float* __restrict__ o_out)
{
    extern __shared__ float smf[];
    float* Qs = smf;
    float* Ks = Qs + 64 * APITCH;
    float* Vs = Ks + 64 * APITCH;
    float* Ps = Vs + 64 * APITCH;

    const int qt = blockIdx.x;
    const int bh = blockIdx.y;
    const int b = bh >> 4;
    const int h = bh & 15;
    const int tid = threadIdx.x;
    const int rg = tid >> 4;
    const int cg = tid & 15;

    for (int e = tid; e < 64 * 64; e += 256) {
        int r = e >> 6, c = e & 63;
        int t = (qt * 64 + r) * Bdim + b;
        Qs[r * APITCH + c] = qkv[(size_t)t * D3 + h * DHdim + c] * 0.125f;
    }

    float m[4], l[4], o[4][4];
#pragma unroll
    for (int i = 0; i < 4; i++) {
        m[i] = -INFINITY; l[i] = 0.f;
#pragma unroll
        for (int j = 0; j < 4; j++) o[i][j] = 0.f;
    }

    for (int kt = 0; kt <= qt; kt++) {
        __syncthreads();
        for (int e = tid; e < 64 * 64; e += 256) {
            int r = e >> 6, c = e & 63;
            int t = (kt * 64 + r) * Bdim + b;
            Ks[r * APITCH + c] = qkv[(size_t)t * D3 + Ddim     + h * DHdim + c];
            Vs[r * APITCH + c] = qkv[(size_t)t * D3 + 2 * Ddim + h * DHdim + c];
        }
        __syncthreads();

        float s[4][4];
#pragma unroll
        for (int i = 0; i < 4; i++)
#pragma unroll
            for (int j = 0; j < 4; j++) s[i][j] = 0.f;

#pragma unroll 4
        for (int k = 0; k < 64; k++) {
            float qv[4], kv[4];
#pragma unroll
            for (int i = 0; i < 4; i++) qv[i] = Qs[(rg * 4 + i) * APITCH + k];
#pragma unroll
            for (int j = 0; j < 4; j++) kv[j] = Ks[(cg * 4 + j) * APITCH + k];
#pragma unroll
            for (int i = 0; i < 4; i++)
#pragma unroll
                for (int j = 0; j < 4; j++) s[i][j] += qv[i] * kv[j];
        }

        if (kt == qt) {
#pragma unroll
            for (int i = 0; i < 4; i++)
#pragma unroll
                for (int j = 0; j < 4; j++)
                    if (cg * 4 + j > rg * 4 + i) s[i][j] = -INFINITY;
        }

#pragma unroll
        for (int i = 0; i < 4; i++) {
            float mx = fmaxf(fmaxf(s[i][0], s[i][1]), fmaxf(s[i][2], s[i][3]));
#pragma unroll
            for (int d = 1; d < 16; d <<= 1) mx = fmaxf(mx, __shfl_xor_sync(0xffffffffu, mx, d));
            float mn = fmaxf(m[i], mx);
            float scale = __expf(m[i] - mn);
            float ls = 0.f;
#pragma unroll
            for (int j = 0; j < 4; j++) { s[i][j] = __expf(s[i][j] - mn); ls += s[i][j]; }
#pragma unroll
            for (int d = 1; d < 16; d <<= 1) ls += __shfl_xor_sync(0xffffffffu, ls, d);
            l[i] = l[i] * scale + ls;
            m[i] = mn;
#pragma unroll
            for (int j = 0; j < 4; j++) {
                o[i][j] *= scale;
                Ps[(rg * 4 + i) * APITCH + cg * 4 + j] = s[i][j];
            }
        }
        __syncthreads();

#pragma unroll 4
        for (int c = 0; c < 64; c++) {
            float pv[4], vv[4];
#pragma unroll
            for (int i = 0; i < 4; i++) pv[i] = Ps[(rg * 4 + i) * APITCH + c];
#pragma unroll
            for (int j = 0; j < 4; j++) vv[j] = Vs[c * APITCH + cg * 4 + j];
#pragma unroll
            for (int i = 0; i < 4; i++)
#pragma unroll
                for (int j = 0; j < 4; j++) o[i][j] += pv[i] * vv[j];
        }
    }

#pragma unroll
    for (int i = 0; i < 4; i++) {
        int r = rg * 4 + i;
        int t = (qt * 64 + r) * Bdim + b;
        float inv = 1.f / l[i];
#pragma unroll
        for (int j = 0; j < 4; j++)
            o_out[(size_t)t * Ddim + h * DHdim + cg * 4 + j] = o[i][j] * inv;
    }
}

// ---------------------------------------------------------------------------
// Fused final: LN2 -> router logits -> gate -> out
// ---------------------------------------------------------------------------
__global__ void __launch_bounds__(256) final_kernel(
    const float* __restrict__ xo, const float* __restrict__ w,
    const float* __restrict__ bprm, const float* __restrict__ gate_w,
    float* __restrict__ out, float* __restrict__ logits)
{
    int t = blockIdx.x;
    int tid = threadIdx.x;
    const float4 v = reinterpret_cast<const float4*>(xo + (size_t)t * Ddim)[tid];

    float s  = v.x + v.y + v.z + v.w;
    float sq = v.x*v.x + v.y*v.y + v.z*v.z + v.w*v.w;
    s  = warp_sum_f(s);
    sq = warp_sum_f(sq);

    __shared__ float sm[16];
    __shared__ float red[3][8];
    __shared__ float bc[3];
    int warp = tid >> 5, lane = tid & 31;
    if (lane == 0) { sm[warp] = s; sm[warp + 8] = sq; }
    __syncthreads();
    if (tid == 0) {
        float a = 0.f, c = 0.f;
#pragma unroll
        for (int i = 0; i < 8; i++) { a += sm[i]; c += sm[i + 8]; }
        float mu = a * (1.f / Ddim);
        float var = c * (1.f / Ddim) - mu * mu;
        bc[0] = mu;
        bc[1] = rsqrtf(var + 1e-5f);
    }
    __syncthreads();
    float mu = bc[0], rs = bc[1];

    const float4 wv = reinterpret_cast<const float4*>(w)[tid];
    const float4 bv = reinterpret_cast<const float4*>(bprm)[tid];
    float hs[4];
    hs[0] = (v.x - mu) * rs * wv.x + bv.x;
    hs[1] = (v.y - mu) * rs * wv.y + bv.y;
    hs[2] = (v.z - mu) * rs * wv.z + bv.z;
    hs[3] = (v.w - mu) * rs * wv.w + bv.w;

    int d = tid * 4;
    float a0 = 0.f, a1 = 0.f, a2 = 0.f;
#pragma unroll
    for (int j = 0; j < 4; j++) {
        a0 += hs[j] * gate_w[0 * Ddim + d + j];
        a1 += hs[j] * gate_w[1 * Ddim + d + j];
        a2 += hs[j] * gate_w[2 * Ddim + d + j];
    }
    a0 = warp_sum_f(a0); a1 = warp_sum_f(a1); a2 = warp_sum_f(a2);
    if (lane == 0) { red[0][warp] = a0; red[1][warp] = a1; red[2][warp] = a2; }
    __syncthreads();
    if (tid == 0) {
        float l0 = 0.f, l1 = 0.f, l2 = 0.f;
#pragma unroll
        for (int i = 0; i < 8; i++) { l0 += red[0][i]; l1 += red[1][i]; l2 += red[2][i]; }
        logits[(size_t)t * 3 + 0] = l0;
        logits[(size_t)t * 3 + 1] = l1;
        logits[(size_t)t * 3 + 2] = l2;
        float hi  = fmaxf(l0, fmaxf(l1, l2));
        float lo  = fminf(l0, fminf(l1, l2));
        float mid = l0 + l1 + l2 - hi - lo;
        bc[2] = 1.f / (1.f + __expf(mid - hi));
    }
    __syncthreads();
    float gate = bc[2];
    float4 ov;
    ov.x = v.x * gate; ov.y = v.y * gate; ov.z = v.z * gate; ov.w = v.w * gate;
    reinterpret_cast<float4*>(out + (size_t)t * Ddim)[tid] = ov;
}

// ---------------------------------------------------------------------------
extern "C" void kernel_launch(void* const* d_in, const int* in_sizes, int n_in,
                              void* d_out, int out_size)
{
    const float* x          = (const float*)d_in[0];
    const float* ln1_w      = (const float*)d_in[1];
    const float* ln1_b      = (const float*)d_in[2];
    const float* ln2_w      = (const float*)d_in[3];
    const float* ln2_b      = (const float*)d_in[4];
    const float* in_proj_w  = (const float*)d_in[5];
    const float* in_proj_b  = (const float*)d_in[6];
    const float* out_proj_w = (const float*)d_in[7];
    const float* out_proj_b = (const float*)d_in[8];
    const float* gate_w     = (const float*)d_in[9];
    // d_in[10..13] = fc_w, fc_b, proj_w, proj_b — DEAD in the reference output.

    float* out    = (float*)d_out;
    float* logits = out + (size_t)Tdim * Ddim;

    float *h, *qkv, *o, *xo;
    cudaGetSymbolAddress((void**)&h,   g_h);
    cudaGetSymbolAddress((void**)&qkv, g_qkv);
    cudaGetSymbolAddress((void**)&o,   g_o);
    cudaGetSymbolAddress((void**)&xo,  g_xo);

    cudaFuncSetAttribute(gemm_mma<0>, cudaFuncAttributeMaxDynamicSharedMemorySize, GM_SMEM_BYTES);
    cudaFuncSetAttribute(gemm_mma<1>, cudaFuncAttributeMaxDynamicSharedMemorySize, GM_SMEM_BYTES);

    // 1) LN1
    ln_kernel<<<Tdim, 256>>>(x, ln1_w, ln1_b, h);

    // 2) QKV = LN1(x) @ in_proj_w.T + b   (mma.sync, split-bf16)
    gemm_mma<0><<<dim3(D3 / 128, Tdim / 128), 256, GM_SMEM_BYTES>>>(
        h, in_proj_w, in_proj_b, nullptr, qkv, Tdim, D3, Ddim);

    // 3) causal attention
    const int attn_smem = 4 * 64 * APITCH * (int)sizeof(float);
    cudaFuncSetAttribute(attn_kernel, cudaFuncAttributeMaxDynamicSharedMemorySize, attn_smem);
    attn_kernel<<<dim3(Sdim / 64, Bdim * Hn), 256, attn_smem>>>(qkv, o);

    // 4) x_attn = x + attn @ out_proj_w.T + b   (mma.sync, split-bf16)
    gemm_mma<1><<<dim3(Ddim / 128, Tdim / 128), 256, GM_SMEM_BYTES>>>(
        o, out_proj_w, out_proj_b, x, xo, Tdim, Ddim, Ddim);

    // 5) LN2 -> router logits -> gate -> out
    final_kernel<<<Tdim, 256>>>(xo, ln2_w, ln2_b, gate_w, out, logits);
}